// round 3
// baseline (speedup 1.0000x reference)
#include <cuda_runtime.h>
#include <cstdint>

// Problem constants
// B=2, S=1024, H=4096, NH=32, NKV=8, HD=128, GROUPS=4
// M = B*S = 2048

// ---------------- scratch (static __device__, no allocations) ----------------
__device__ static float g_Q[2 * 32 * 1024 * 128];   // [B,NH,S,HD]  33.5 MB
__device__ static float g_K[2 * 8 * 1024 * 128];    // [B,NKV,S,HD]  8.4 MB
__device__ static float g_V[2 * 8 * 1024 * 128];    // [B,NKV,S,HD]  8.4 MB
__device__ static float g_P[64 * 1024 * 1024];      // [B*NH,S,S]   256 MB (scores/probs)
__device__ static float g_AO[2048 * 4096];          // [B*S, NH*HD] 33.5 MB

// =============================================================================
// Kernel 1: fused QKV projection GEMM
//   Y[m, n] = sum_k X[m,k] * W[n,k] * scale[n] (+ bias[n])
//   X: [2048, 4096] f32.  W region: n<4096 -> Wq, n<5120 -> Wk, else Wv.
//   Output scattered into head-major layouts g_Q/g_K/g_V.
//   Tile 128x128x8, 256 threads, 8x8 microtile.
// =============================================================================
__global__ __launch_bounds__(256) void qkv_kernel(
    const float* __restrict__ X,
    const int* __restrict__ wq, const float* __restrict__ sq, const float* __restrict__ bq,
    const int* __restrict__ wk, const float* __restrict__ sk, const float* __restrict__ bkb,
    const int* __restrict__ wv, const float* __restrict__ sv)
{
    __shared__ float As[8][128];
    __shared__ float Bs[8][128];

    const int tx = threadIdx.x, ty = threadIdx.y;
    const int tid = ty * 16 + tx;
    const int n0 = blockIdx.x * 128;     // 0..6143
    const int m0 = blockIdx.y * 128;     // 0..2047

    const int* W; const float* scale; const float* bias; int nloc; int region;
    if (n0 < 4096)      { W = wq; scale = sq; bias = bq;      nloc = n0;        region = 0; }
    else if (n0 < 5120) { W = wk; scale = sk; bias = bkb;     nloc = n0 - 4096; region = 1; }
    else                { W = wv; scale = sv; bias = nullptr; nloc = n0 - 5120; region = 2; }

    const int lrow = tid >> 1;            // 0..127
    const int lkq  = (tid & 1) * 4;       // 0 or 4
    const float* Aptr = X + (size_t)(m0 + lrow) * 4096 + lkq;
    const int*   Bptr = W + (size_t)(nloc + lrow) * 4096 + lkq;

    float acc[8][8];
#pragma unroll
    for (int i = 0; i < 8; ++i)
#pragma unroll
        for (int j = 0; j < 8; ++j) acc[i][j] = 0.f;

    for (int k0 = 0; k0 < 4096; k0 += 8) {
        float4 av = *reinterpret_cast<const float4*>(Aptr + k0);
        int4   wv4 = *reinterpret_cast<const int4*>(Bptr + k0);
        As[lkq + 0][lrow] = av.x;
        As[lkq + 1][lrow] = av.y;
        As[lkq + 2][lrow] = av.z;
        As[lkq + 3][lrow] = av.w;
        Bs[lkq + 0][lrow] = (float)wv4.x;
        Bs[lkq + 1][lrow] = (float)wv4.y;
        Bs[lkq + 2][lrow] = (float)wv4.z;
        Bs[lkq + 3][lrow] = (float)wv4.w;
        __syncthreads();
#pragma unroll
        for (int kk = 0; kk < 8; ++kk) {
            float ar[8], br[8];
            *reinterpret_cast<float4*>(&ar[0]) = *reinterpret_cast<const float4*>(&As[kk][ty * 8]);
            *reinterpret_cast<float4*>(&ar[4]) = *reinterpret_cast<const float4*>(&As[kk][ty * 8 + 4]);
            *reinterpret_cast<float4*>(&br[0]) = *reinterpret_cast<const float4*>(&Bs[kk][tx * 8]);
            *reinterpret_cast<float4*>(&br[4]) = *reinterpret_cast<const float4*>(&Bs[kk][tx * 8 + 4]);
#pragma unroll
            for (int i = 0; i < 8; ++i)
#pragma unroll
                for (int j = 0; j < 8; ++j) acc[i][j] += ar[i] * br[j];
        }
        __syncthreads();
    }

    // epilogue: dequant + bias + head-transposed scatter
    float sc8[8], bi8[8];
#pragma unroll
    for (int j = 0; j < 8; ++j) {
        int c = tx * 8 + j;
        sc8[j] = scale[nloc + c];
        bi8[j] = bias ? bias[nloc + c] : 0.f;
    }
    const int head = nloc >> 7;   // tile spans exactly one head (128 cols)
#pragma unroll
    for (int i = 0; i < 8; ++i) {
        int m = m0 + ty * 8 + i;
        int b = m >> 10, s = m & 1023;
        float* op;
        if (region == 0)      op = g_Q + ((size_t)((b * 32 + head) * 1024 + s)) * 128;
        else if (region == 1) op = g_K + ((size_t)((b * 8 + head) * 1024 + s)) * 128;
        else                  op = g_V + ((size_t)((b * 8 + head) * 1024 + s)) * 128;
#pragma unroll
        for (int j = 0; j < 8; ++j)
            op[tx * 8 + j] = acc[i][j] * sc8[j] + bi8[j];
    }
}

// =============================================================================
// Kernel 2: scores S = Q K^T / sqrt(HD) + mask     per (b,h): [1024,1024,K=128]
// =============================================================================
__global__ __launch_bounds__(256) void score_kernel(const float* __restrict__ mask)
{
    __shared__ float As[8][128];
    __shared__ float Bs[8][128];

    const int tx = threadIdx.x, ty = threadIdx.y;
    const int tid = ty * 16 + tx;
    const int n0 = blockIdx.x * 128;
    const int m0 = blockIdx.y * 128;
    const int z  = blockIdx.z;           // 0..63 = b*32 + h
    const int b = z >> 5, h = z & 31, kvh = h >> 2;

    const float* Qp = g_Q + (size_t)(b * 32 + h)  * 1024 * 128;
    const float* Kp = g_K + (size_t)(b * 8 + kvh) * 1024 * 128;

    const int lrow = tid >> 1;
    const int lkq  = (tid & 1) * 4;

    float acc[8][8];
#pragma unroll
    for (int i = 0; i < 8; ++i)
#pragma unroll
        for (int j = 0; j < 8; ++j) acc[i][j] = 0.f;

    for (int k0 = 0; k0 < 128; k0 += 8) {
        float4 av = *reinterpret_cast<const float4*>(Qp + (size_t)(m0 + lrow) * 128 + k0 + lkq);
        float4 bv = *reinterpret_cast<const float4*>(Kp + (size_t)(n0 + lrow) * 128 + k0 + lkq);
        As[lkq + 0][lrow] = av.x; As[lkq + 1][lrow] = av.y;
        As[lkq + 2][lrow] = av.z; As[lkq + 3][lrow] = av.w;
        Bs[lkq + 0][lrow] = bv.x; Bs[lkq + 1][lrow] = bv.y;
        Bs[lkq + 2][lrow] = bv.z; Bs[lkq + 3][lrow] = bv.w;
        __syncthreads();
#pragma unroll
        for (int kk = 0; kk < 8; ++kk) {
            float ar[8], br[8];
            *reinterpret_cast<float4*>(&ar[0]) = *reinterpret_cast<const float4*>(&As[kk][ty * 8]);
            *reinterpret_cast<float4*>(&ar[4]) = *reinterpret_cast<const float4*>(&As[kk][ty * 8 + 4]);
            *reinterpret_cast<float4*>(&br[0]) = *reinterpret_cast<const float4*>(&Bs[kk][tx * 8]);
            *reinterpret_cast<float4*>(&br[4]) = *reinterpret_cast<const float4*>(&Bs[kk][tx * 8 + 4]);
#pragma unroll
            for (int i = 0; i < 8; ++i)
#pragma unroll
                for (int j = 0; j < 8; ++j) acc[i][j] += ar[i] * br[j];
        }
        __syncthreads();
    }

    const float sscale = 0.08838834764831845f;  // 1/sqrt(128)
#pragma unroll
    for (int i = 0; i < 8; ++i) {
        int q = m0 + ty * 8 + i;
        const float* mp = mask + ((size_t)b * 1024 + q) * 1024 + n0 + tx * 8;
        float* op = g_P + ((size_t)z * 1024 + q) * 1024 + n0 + tx * 8;
#pragma unroll
        for (int j = 0; j < 8; ++j)
            op[j] = acc[i][j] * sscale + mp[j];
    }
}

// =============================================================================
// Kernel 3: row softmax over g_P, in place. One warp per 1024-elem row.
// =============================================================================
__global__ __launch_bounds__(256) void softmax_kernel()
{
    const int warp = threadIdx.x >> 5, lane = threadIdx.x & 31;
    const size_t row = (size_t)blockIdx.x * 8 + warp;    // < 65536
    float* p = g_P + row * 1024;

    float4 v[8];
    float mx = -3.4e38f;
#pragma unroll
    for (int i = 0; i < 8; ++i) {
        v[i] = *reinterpret_cast<const float4*>(p + (size_t)(lane + 32 * i) * 4);
        mx = fmaxf(mx, fmaxf(fmaxf(v[i].x, v[i].y), fmaxf(v[i].z, v[i].w)));
    }
#pragma unroll
    for (int o = 16; o > 0; o >>= 1) mx = fmaxf(mx, __shfl_xor_sync(0xffffffffu, mx, o));

    float sum = 0.f;
#pragma unroll
    for (int i = 0; i < 8; ++i) {
        v[i].x = __expf(v[i].x - mx);
        v[i].y = __expf(v[i].y - mx);
        v[i].z = __expf(v[i].z - mx);
        v[i].w = __expf(v[i].w - mx);
        sum += v[i].x + v[i].y + v[i].z + v[i].w;
    }
#pragma unroll
    for (int o = 16; o > 0; o >>= 1) sum += __shfl_xor_sync(0xffffffffu, sum, o);

    const float inv = 1.f / sum;
#pragma unroll
    for (int i = 0; i < 8; ++i) {
        v[i].x *= inv; v[i].y *= inv; v[i].z *= inv; v[i].w *= inv;
        *reinterpret_cast<float4*>(p + (size_t)(lane + 32 * i) * 4) = v[i];
    }
}

// =============================================================================
// Kernel 4: O_attn = P @ V   per (b,h): M=1024, N=128, K=1024
//   Writes g_AO in [B*S, NH*HD] layout (ready for O projection).
// =============================================================================
__global__ __launch_bounds__(256) void pv_kernel()
{
    __shared__ float As[8][128];
    __shared__ float Bs[8][128];

    const int tx = threadIdx.x, ty = threadIdx.y;
    const int tid = ty * 16 + tx;
    const int m0 = blockIdx.y * 128;
    const int z  = blockIdx.z;
    const int b = z >> 5, h = z & 31, kvh = h >> 2;

    const float* Pp = g_P + (size_t)z * 1024 * 1024;
    const float* Vp = g_V + (size_t)(b * 8 + kvh) * 1024 * 128;

    const int lrow = tid >> 1;
    const int lkq  = (tid & 1) * 4;
    const int bkk  = tid >> 5;         // 0..7
    const int bf4  = (tid & 31) * 4;   // 0..124

    float acc[8][8];
#pragma unroll
    for (int i = 0; i < 8; ++i)
#pragma unroll
        for (int j = 0; j < 8; ++j) acc[i][j] = 0.f;

    for (int k0 = 0; k0 < 1024; k0 += 8) {
        float4 av = *reinterpret_cast<const float4*>(Pp + (size_t)(m0 + lrow) * 1024 + k0 + lkq);
        As[lkq + 0][lrow] = av.x; As[lkq + 1][lrow] = av.y;
        As[lkq + 2][lrow] = av.z; As[lkq + 3][lrow] = av.w;
        // V tile: rows are k, cols are d (natural [K][N] layout)
        float4 bv = *reinterpret_cast<const float4*>(Vp + (size_t)(k0 + bkk) * 128 + bf4);
        *reinterpret_cast<float4*>(&Bs[bkk][bf4]) = bv;
        __syncthreads();
#pragma unroll
        for (int kk = 0; kk < 8; ++kk) {
            float ar[8], br[8];
            *reinterpret_cast<float4*>(&ar[0]) = *reinterpret_cast<const float4*>(&As[kk][ty * 8]);
            *reinterpret_cast<float4*>(&ar[4]) = *reinterpret_cast<const float4*>(&As[kk][ty * 8 + 4]);
            *reinterpret_cast<float4*>(&br[0]) = *reinterpret_cast<const float4*>(&Bs[kk][tx * 8]);
            *reinterpret_cast<float4*>(&br[4]) = *reinterpret_cast<const float4*>(&Bs[kk][tx * 8 + 4]);
#pragma unroll
            for (int i = 0; i < 8; ++i)
#pragma unroll
                for (int j = 0; j < 8; ++j) acc[i][j] += ar[i] * br[j];
        }
        __syncthreads();
    }

#pragma unroll
    for (int i = 0; i < 8; ++i) {
        int q = m0 + ty * 8 + i;
        float* op = g_AO + ((size_t)(b * 1024 + q)) * 4096 + h * 128 + tx * 8;
#pragma unroll
        for (int j = 0; j < 8; ++j) op[j] = acc[i][j];
    }
}

// =============================================================================
// Kernel 5: output projection  out = AO @ Wo^T * so    [2048,4096] x [4096,4096]
// =============================================================================
__global__ __launch_bounds__(256) void o_kernel(
    const int* __restrict__ wo, const float* __restrict__ so, float* __restrict__ out)
{
    __shared__ float As[8][128];
    __shared__ float Bs[8][128];

    const int tx = threadIdx.x, ty = threadIdx.y;
    const int tid = ty * 16 + tx;
    const int n0 = blockIdx.x * 128;
    const int m0 = blockIdx.y * 128;

    const int lrow = tid >> 1;
    const int lkq  = (tid & 1) * 4;
    const float* Aptr = g_AO + (size_t)(m0 + lrow) * 4096 + lkq;
    const int*   Bptr = wo + (size_t)(n0 + lrow) * 4096 + lkq;

    float acc[8][8];
#pragma unroll
    for (int i = 0; i < 8; ++i)
#pragma unroll
        for (int j = 0; j < 8; ++j) acc[i][j] = 0.f;

    for (int k0 = 0; k0 < 4096; k0 += 8) {
        float4 av = *reinterpret_cast<const float4*>(Aptr + k0);
        int4   wv4 = *reinterpret_cast<const int4*>(Bptr + k0);
        As[lkq + 0][lrow] = av.x; As[lkq + 1][lrow] = av.y;
        As[lkq + 2][lrow] = av.z; As[lkq + 3][lrow] = av.w;
        Bs[lkq + 0][lrow] = (float)wv4.x; Bs[lkq + 1][lrow] = (float)wv4.y;
        Bs[lkq + 2][lrow] = (float)wv4.z; Bs[lkq + 3][lrow] = (float)wv4.w;
        __syncthreads();
#pragma unroll
        for (int kk = 0; kk < 8; ++kk) {
            float ar[8], br[8];
            *reinterpret_cast<float4*>(&ar[0]) = *reinterpret_cast<const float4*>(&As[kk][ty * 8]);
            *reinterpret_cast<float4*>(&ar[4]) = *reinterpret_cast<const float4*>(&As[kk][ty * 8 + 4]);
            *reinterpret_cast<float4*>(&br[0]) = *reinterpret_cast<const float4*>(&Bs[kk][tx * 8]);
            *reinterpret_cast<float4*>(&br[4]) = *reinterpret_cast<const float4*>(&Bs[kk][tx * 8 + 4]);
#pragma unroll
            for (int i = 0; i < 8; ++i)
#pragma unroll
                for (int j = 0; j < 8; ++j) acc[i][j] += ar[i] * br[j];
        }
        __syncthreads();
    }

    float sc8[8];
#pragma unroll
    for (int j = 0; j < 8; ++j) sc8[j] = so[n0 + tx * 8 + j];
#pragma unroll
    for (int i = 0; i < 8; ++i) {
        int m = m0 + ty * 8 + i;
        float* op = out + (size_t)m * 4096 + n0 + tx * 8;
#pragma unroll
        for (int j = 0; j < 8; ++j) op[j] = acc[i][j] * sc8[j];
    }
}

// =============================================================================
extern "C" void kernel_launch(void* const* d_in, const int* in_sizes, int n_in,
                              void* d_out, int out_size)
{
    const float* X    = (const float*)d_in[0];   // hidden_states [2,1024,4096]
    const float* mask = (const float*)d_in[1];   // attention_mask [2,1,1024,1024]
    const int*   wq   = (const int*)d_in[2];
    const float* sq   = (const float*)d_in[3];
    const float* bq   = (const float*)d_in[4];
    const int*   wk   = (const int*)d_in[5];
    const float* sk   = (const float*)d_in[6];
    const float* bk   = (const float*)d_in[7];
    const int*   wv   = (const int*)d_in[8];
    const float* sv   = (const float*)d_in[9];
    const int*   wo   = (const int*)d_in[10];
    const float* so   = (const float*)d_in[11];
    float* out = (float*)d_out;

    dim3 blk(16, 16);
    qkv_kernel<<<dim3(48, 16), blk>>>(X, wq, sq, bq, wk, sk, bk, wv, sv);
    score_kernel<<<dim3(8, 8, 64), blk>>>(mask);
    softmax_kernel<<<8192, 256>>>();
    pv_kernel<<<dim3(1, 8, 64), blk>>>();
    o_kernel<<<dim3(32, 16), blk>>>(wo, so, out);
}

// round 4
// speedup vs baseline: 3.8729x; 3.8729x over previous
#include <cuda_runtime.h>
#include <cstdint>

// B=2, S=1024, H=4096, NH=32, NKV=8, HD=128, GROUPS=4, M=B*S=2048
// All GEMMs on tensor cores via mma.sync.m16n8k8.tf32.
// Weights (int8-valued) are EXACT in tf32; activations rounded once (RNA) at
// producer epilogues -> only ~2.8e-4 relative noise per GEMM operand.

// ---------------- scratch (static __device__, no allocations) ----------------
__device__ static float g_Xc[2048 * 4096];            //  32 MB tf32-rounded X
__device__ static float g_Wqkv[6144 * 4096];          // 100 MB float weights (q,k,v concat)
__device__ static float g_Wof[4096 * 4096];           //  64 MB float Wo
__device__ static float g_Q[2 * 32 * 1024 * 128];     //  33.5 MB [B,NH,S,HD]   (tf32 vals)
__device__ static float g_K[2 * 8 * 1024 * 128];      //   8.4 MB [B,NKV,S,HD]  (tf32 vals)
__device__ static float g_V[2 * 8 * 1024 * 128];      //   8.4 MB
__device__ static float g_P[64 * 1024 * 1024];        // 256 MB [B*NH,S,S] scores->probs
__device__ static float g_AO[2048 * 4096];            //  33.5 MB (tf32 vals)

// ---------------- helpers ----------------
__device__ __forceinline__ float to_tf32(float x) {
    uint32_t u;
    asm("cvt.rna.tf32.f32 %0, %1;" : "=r"(u) : "f"(x));
    return __uint_as_float(u);
}

__device__ __forceinline__ void cpa16(float* dst, const float* src) {
    uint32_t s = static_cast<uint32_t>(__cvta_generic_to_shared(dst));
    asm volatile("cp.async.cg.shared.global [%0], [%1], 16;\n" :: "r"(s), "l"(src));
}
#define CP_COMMIT() asm volatile("cp.async.commit_group;\n")
#define CP_WAIT1()  asm volatile("cp.async.wait_group 1;\n")
#define CP_WAIT0()  asm volatile("cp.async.wait_group 0;\n")

__device__ __forceinline__ void mma_tf32(float d[4], const uint32_t a[4], const uint32_t b[2]) {
    asm volatile(
        "mma.sync.aligned.m16n8k8.row.col.f32.tf32.tf32.f32 "
        "{%0,%1,%2,%3},{%4,%5,%6,%7},{%8,%9},{%0,%1,%2,%3};\n"
        : "+f"(d[0]), "+f"(d[1]), "+f"(d[2]), "+f"(d[3])
        : "r"(a[0]), "r"(a[1]), "r"(a[2]), "r"(a[3]), "r"(b[0]), "r"(b[1]));
}

// smem layouts (floats): A [256][36] (row-major, pad 4), B_nk [128][36], B_kn [32][136]
#define ASZ  (256 * 36)
#define BSZN (128 * 36)
#define BSZK (32 * 136)

// tile loaders (src pre-offset to (m0,k0))
__device__ __forceinline__ void load_tileA(float* dst, const float* src, int rs, int t) {
    int c = t & 7, mb = t >> 3;
#pragma unroll
    for (int p = 0; p < 8; ++p) {
        int m = mb + 32 * p;
        cpa16(dst + m * 36 + 4 * c, src + (size_t)m * rs + 4 * c);
    }
}
__device__ __forceinline__ void load_tileB_nk(float* dst, const float* src, int rs, int t) {
    int c = t & 7, nb = t >> 3;
#pragma unroll
    for (int p = 0; p < 4; ++p) {
        int n = nb + 32 * p;
        cpa16(dst + n * 36 + 4 * c, src + (size_t)n * rs + 4 * c);
    }
}
__device__ __forceinline__ void load_tileB_kn(float* dst, const float* src, int t) {
    int c = t & 31, kb = t >> 5;
#pragma unroll
    for (int p = 0; p < 4; ++p) {
        int k = kb + 8 * p;
        cpa16(dst + k * 136 + 4 * c, src + (size_t)k * 128 + 4 * c);
    }
}

// compute one k32 chunk. warp tile 64x64: 4 m-tiles (16) x 8 n-tiles (8).
template<bool BKN>
__device__ __forceinline__ void compute_k32(const float* sA, const float* sB,
                                            float acc[4][8][4], int lane, int wm, int wn) {
    const int lr = lane >> 2, lc = lane & 3;
#pragma unroll
    for (int s = 0; s < 4; ++s) {
        uint32_t af[4][4], bf[8][2];
#pragma unroll
        for (int i = 0; i < 4; ++i) {
            const float* p = sA + (wm + 16 * i + lr) * 36 + 8 * s + lc;
            af[i][0] = __float_as_uint(p[0]);
            af[i][1] = __float_as_uint(p[8 * 36]);
            af[i][2] = __float_as_uint(p[4]);
            af[i][3] = __float_as_uint(p[8 * 36 + 4]);
        }
#pragma unroll
        for (int j = 0; j < 8; ++j) {
            if (BKN) {
                const float* p = sB + (8 * s + lc) * 136 + wn + 8 * j + lr;
                bf[j][0] = __float_as_uint(p[0]);
                bf[j][1] = __float_as_uint(p[4 * 136]);
            } else {
                const float* p = sB + (wn + 8 * j + lr) * 36 + 8 * s + lc;
                bf[j][0] = __float_as_uint(p[0]);
                bf[j][1] = __float_as_uint(p[4]);
            }
        }
#pragma unroll
        for (int i = 0; i < 4; ++i)
#pragma unroll
            for (int j = 0; j < 8; ++j)
                mma_tf32(acc[i][j], af[i], bf[j]);
    }
}

// ---------------- prep kernels ----------------
__global__ __launch_bounds__(256) void i2f_kernel(const int* __restrict__ src,
                                                  float* __restrict__ dst, int n4) {
    int i = blockIdx.x * 256 + threadIdx.x;
    if (i < n4) {
        int4 v = reinterpret_cast<const int4*>(src)[i];
        float4 o = make_float4((float)v.x, (float)v.y, (float)v.z, (float)v.w);
        reinterpret_cast<float4*>(dst)[i] = o;
    }
}
__global__ __launch_bounds__(256) void cvtx_kernel(const float* __restrict__ src,
                                                   float* __restrict__ dst, int n4) {
    int i = blockIdx.x * 256 + threadIdx.x;
    if (i < n4) {
        float4 v = reinterpret_cast<const float4*>(src)[i];
        v.x = to_tf32(v.x); v.y = to_tf32(v.y); v.z = to_tf32(v.z); v.w = to_tf32(v.w);
        reinterpret_cast<float4*>(dst)[i] = v;
    }
}

// ---------------- GEMM 1: fused QKV projection ----------------
// C[m,n] = Xc[m,:] . Wqkv[n,:], n<4096 Q, <5120 K, else V.  grid (48, 8)
__global__ __launch_bounds__(256) void qkv_mma(
    const float* __restrict__ sq, const float* __restrict__ bq,
    const float* __restrict__ sk, const float* __restrict__ bk,
    const float* __restrict__ sv)
{
    extern __shared__ float sm[];
    float* sA = sm;
    float* sB = sm + 2 * ASZ;
    const int t = threadIdx.x, lane = t & 31, w = t >> 5;
    const int wm = (w >> 1) * 64, wn = (w & 1) * 64;
    const int m0 = blockIdx.y * 256, n0 = blockIdx.x * 128;

    float acc[4][8][4];
#pragma unroll
    for (int i = 0; i < 4; ++i)
#pragma unroll
        for (int j = 0; j < 8; ++j)
#pragma unroll
            for (int q = 0; q < 4; ++q) acc[i][j][q] = 0.f;

    const float* Ab = g_Xc + (size_t)m0 * 4096;
    const float* Bb = g_Wqkv + (size_t)n0 * 4096;

    load_tileA(sA, Ab, 4096, t);
    load_tileB_nk(sB, Bb, 4096, t);
    CP_COMMIT();
    for (int it = 0; it < 128; ++it) {
        if (it + 1 < 128) {
            int nb = (it + 1) & 1;
            load_tileA(sA + nb * ASZ, Ab + (it + 1) * 32, 4096, t);
            load_tileB_nk(sB + nb * BSZN, Bb + (it + 1) * 32, 4096, t);
            CP_COMMIT();
            CP_WAIT1();
        } else CP_WAIT0();
        __syncthreads();
        int buf = it & 1;
        compute_k32<false>(sA + buf * ASZ, sB + buf * BSZN, acc, lane, wm, wn);
        __syncthreads();
    }

    // epilogue: dequant + bias + cvt tf32 + head scatter
    int region, nloc;
    const float* scale; const float* bias;
    if (n0 < 4096)      { region = 0; nloc = n0;        scale = sq; bias = bq; }
    else if (n0 < 5120) { region = 1; nloc = n0 - 4096; scale = sk; bias = bk; }
    else                { region = 2; nloc = n0 - 5120; scale = sv; bias = nullptr; }
    const int head = nloc >> 7;
    const int lr = lane >> 2, lc = lane & 3;
#pragma unroll
    for (int j = 0; j < 8; ++j) {
        int col = wn + 8 * j + 2 * lc;                 // 0..127 within head
        int nl = nloc + col;
        float sc0 = scale[nl], sc1 = scale[nl + 1];
        float bb0 = bias ? bias[nl] : 0.f, bb1 = bias ? bias[nl + 1] : 0.f;
#pragma unroll
        for (int i = 0; i < 4; ++i) {
#pragma unroll
            for (int h2 = 0; h2 < 2; ++h2) {
                int m = m0 + wm + 16 * i + lr + 8 * h2;
                int b = m >> 10, s = m & 1023;
                float v0 = to_tf32(acc[i][j][2 * h2 + 0] * sc0 + bb0);
                float v1 = to_tf32(acc[i][j][2 * h2 + 1] * sc1 + bb1);
                float* dst;
                if (region == 0)      dst = g_Q + ((size_t)((b * 32 + head) * 1024 + s)) * 128 + col;
                else if (region == 1) dst = g_K + ((size_t)((b * 8 + head) * 1024 + s)) * 128 + col;
                else                  dst = g_V + ((size_t)((b * 8 + head) * 1024 + s)) * 128 + col;
                *reinterpret_cast<float2*>(dst) = make_float2(v0, v1);
            }
        }
    }
}

// ---------------- GEMM 2: scores = Q K^T / sqrt(128) + mask ----------------
// grid (8, 4, 64)
__global__ __launch_bounds__(256) void score_mma(const float* __restrict__ mask)
{
    extern __shared__ float sm[];
    float* sA = sm;
    float* sB = sm + 2 * ASZ;
    const int t = threadIdx.x, lane = t & 31, w = t >> 5;
    const int wm = (w >> 1) * 64, wn = (w & 1) * 64;
    const int m0 = blockIdx.y * 256, n0 = blockIdx.x * 128;
    const int z = blockIdx.z, b = z >> 5, h = z & 31, kvh = h >> 2;

    const float* Qp = g_Q + (size_t)(b * 32 + h) * 131072;
    const float* Kp = g_K + (size_t)(b * 8 + kvh) * 131072;

    float acc[4][8][4];
#pragma unroll
    for (int i = 0; i < 4; ++i)
#pragma unroll
        for (int j = 0; j < 8; ++j)
#pragma unroll
            for (int q = 0; q < 4; ++q) acc[i][j][q] = 0.f;

    const float* Ab = Qp + (size_t)m0 * 128;
    const float* Bb = Kp + (size_t)n0 * 128;
    load_tileA(sA, Ab, 128, t);
    load_tileB_nk(sB, Bb, 128, t);
    CP_COMMIT();
    for (int it = 0; it < 4; ++it) {
        if (it + 1 < 4) {
            int nb = (it + 1) & 1;
            load_tileA(sA + nb * ASZ, Ab + (it + 1) * 32, 128, t);
            load_tileB_nk(sB + nb * BSZN, Bb + (it + 1) * 32, 128, t);
            CP_COMMIT();
            CP_WAIT1();
        } else CP_WAIT0();
        __syncthreads();
        int buf = it & 1;
        compute_k32<false>(sA + buf * ASZ, sB + buf * BSZN, acc, lane, wm, wn);
        __syncthreads();
    }

    const float sscale = 0.08838834764831845f;
    const int lr = lane >> 2, lc = lane & 3;
#pragma unroll
    for (int i = 0; i < 4; ++i) {
#pragma unroll
        for (int h2 = 0; h2 < 2; ++h2) {
            int q = m0 + wm + 16 * i + lr + 8 * h2;
            const float* mrow = mask + ((size_t)b << 20) + (size_t)q * 1024;
            float* orow = g_P + ((size_t)z << 20) + (size_t)q * 1024;
#pragma unroll
            for (int j = 0; j < 8; ++j) {
                int col = n0 + wn + 8 * j + 2 * lc;
                float2 mk = *reinterpret_cast<const float2*>(mrow + col);
                float2 o = make_float2(acc[i][j][2 * h2 + 0] * sscale + mk.x,
                                       acc[i][j][2 * h2 + 1] * sscale + mk.y);
                *reinterpret_cast<float2*>(orow + col) = o;
            }
        }
    }
}

// ---------------- softmax (in place, emits tf32-rounded probs) ----------------
__global__ __launch_bounds__(256) void softmax_kernel()
{
    const int warp = threadIdx.x >> 5, lane = threadIdx.x & 31;
    const size_t row = (size_t)blockIdx.x * 8 + warp;
    float* p = g_P + row * 1024;

    float4 v[8];
    float mx = -3.4e38f;
#pragma unroll
    for (int i = 0; i < 8; ++i) {
        v[i] = *reinterpret_cast<const float4*>(p + (size_t)(lane + 32 * i) * 4);
        mx = fmaxf(mx, fmaxf(fmaxf(v[i].x, v[i].y), fmaxf(v[i].z, v[i].w)));
    }
#pragma unroll
    for (int o = 16; o > 0; o >>= 1) mx = fmaxf(mx, __shfl_xor_sync(0xffffffffu, mx, o));

    float sum = 0.f;
#pragma unroll
    for (int i = 0; i < 8; ++i) {
        v[i].x = __expf(v[i].x - mx); v[i].y = __expf(v[i].y - mx);
        v[i].z = __expf(v[i].z - mx); v[i].w = __expf(v[i].w - mx);
        sum += v[i].x + v[i].y + v[i].z + v[i].w;
    }
#pragma unroll
    for (int o = 16; o > 0; o >>= 1) sum += __shfl_xor_sync(0xffffffffu, sum, o);

    const float inv = 1.f / sum;
#pragma unroll
    for (int i = 0; i < 8; ++i) {
        v[i].x = to_tf32(v[i].x * inv); v[i].y = to_tf32(v[i].y * inv);
        v[i].z = to_tf32(v[i].z * inv); v[i].w = to_tf32(v[i].w * inv);
        *reinterpret_cast<float4*>(p + (size_t)(lane + 32 * i) * 4) = v[i];
    }
}

// ---------------- GEMM 3: AO = P @ V ---------------- grid (1, 4, 64)
__global__ __launch_bounds__(256) void pv_mma()
{
    extern __shared__ float sm[];
    float* sA = sm;
    float* sB = sm + 2 * ASZ;
    const int t = threadIdx.x, lane = t & 31, w = t >> 5;
    const int wm = (w >> 1) * 64, wn = (w & 1) * 64;
    const int m0 = blockIdx.y * 256;
    const int z = blockIdx.z, b = z >> 5, h = z & 31, kvh = h >> 2;

    const float* Pp = g_P + ((size_t)z << 20);
    const float* Vp = g_V + (size_t)(b * 8 + kvh) * 131072;

    float acc[4][8][4];
#pragma unroll
    for (int i = 0; i < 4; ++i)
#pragma unroll
        for (int j = 0; j < 8; ++j)
#pragma unroll
            for (int q = 0; q < 4; ++q) acc[i][j][q] = 0.f;

    const float* Ab = Pp + (size_t)m0 * 1024;
    load_tileA(sA, Ab, 1024, t);
    load_tileB_kn(sB, Vp, t);
    CP_COMMIT();
    for (int it = 0; it < 32; ++it) {
        if (it + 1 < 32) {
            int nb = (it + 1) & 1;
            load_tileA(sA + nb * ASZ, Ab + (it + 1) * 32, 1024, t);
            load_tileB_kn(sB + nb * BSZK, Vp + (size_t)(it + 1) * 32 * 128, t);
            CP_COMMIT();
            CP_WAIT1();
        } else CP_WAIT0();
        __syncthreads();
        int buf = it & 1;
        compute_k32<true>(sA + buf * ASZ, sB + buf * BSZK, acc, lane, wm, wn);
        __syncthreads();
    }

    const int lr = lane >> 2, lc = lane & 3;
#pragma unroll
    for (int i = 0; i < 4; ++i) {
#pragma unroll
        for (int h2 = 0; h2 < 2; ++h2) {
            int q = m0 + wm + 16 * i + lr + 8 * h2;
            float* orow = g_AO + ((size_t)(b * 1024 + q)) * 4096 + h * 128;
#pragma unroll
            for (int j = 0; j < 8; ++j) {
                int col = wn + 8 * j + 2 * lc;
                float2 o = make_float2(to_tf32(acc[i][j][2 * h2 + 0]),
                                       to_tf32(acc[i][j][2 * h2 + 1]));
                *reinterpret_cast<float2*>(orow + col) = o;
            }
        }
    }
}

// ---------------- GEMM 4: out = AO @ Wo^T * so ---------------- grid (32, 8)
__global__ __launch_bounds__(256) void o_mma(const float* __restrict__ so,
                                             float* __restrict__ out)
{
    extern __shared__ float sm[];
    float* sA = sm;
    float* sB = sm + 2 * ASZ;
    const int t = threadIdx.x, lane = t & 31, w = t >> 5;
    const int wm = (w >> 1) * 64, wn = (w & 1) * 64;
    const int m0 = blockIdx.y * 256, n0 = blockIdx.x * 128;

    float acc[4][8][4];
#pragma unroll
    for (int i = 0; i < 4; ++i)
#pragma unroll
        for (int j = 0; j < 8; ++j)
#pragma unroll
            for (int q = 0; q < 4; ++q) acc[i][j][q] = 0.f;

    const float* Ab = g_AO + (size_t)m0 * 4096;
    const float* Bb = g_Wof + (size_t)n0 * 4096;
    load_tileA(sA, Ab, 4096, t);
    load_tileB_nk(sB, Bb, 4096, t);
    CP_COMMIT();
    for (int it = 0; it < 128; ++it) {
        if (it + 1 < 128) {
            int nb = (it + 1) & 1;
            load_tileA(sA + nb * ASZ, Ab + (it + 1) * 32, 4096, t);
            load_tileB_nk(sB + nb * BSZN, Bb + (it + 1) * 32, 4096, t);
            CP_COMMIT();
            CP_WAIT1();
        } else CP_WAIT0();
        __syncthreads();
        int buf = it & 1;
        compute_k32<false>(sA + buf * ASZ, sB + buf * BSZN, acc, lane, wm, wn);
        __syncthreads();
    }

    const int lr = lane >> 2, lc = lane & 3;
#pragma unroll
    for (int j = 0; j < 8; ++j) {
        int col = n0 + wn + 8 * j + 2 * lc;
        float sc0 = so[col], sc1 = so[col + 1];
#pragma unroll
        for (int i = 0; i < 4; ++i) {
#pragma unroll
            for (int h2 = 0; h2 < 2; ++h2) {
                int m = m0 + wm + 16 * i + lr + 8 * h2;
                float2 o = make_float2(acc[i][j][2 * h2 + 0] * sc0,
                                       acc[i][j][2 * h2 + 1] * sc1);
                *reinterpret_cast<float2*>(out + (size_t)m * 4096 + col) = o;
            }
        }
    }
}

// =============================================================================
extern "C" void kernel_launch(void* const* d_in, const int* in_sizes, int n_in,
                              void* d_out, int out_size)
{
    const float* X    = (const float*)d_in[0];
    const float* mask = (const float*)d_in[1];
    const int*   wq   = (const int*)d_in[2];
    const float* sq   = (const float*)d_in[3];
    const float* bq   = (const float*)d_in[4];
    const int*   wk   = (const int*)d_in[5];
    const float* sk   = (const float*)d_in[6];
    const float* bk   = (const float*)d_in[7];
    const int*   wv   = (const int*)d_in[8];
    const float* sv   = (const float*)d_in[9];
    const int*   wo   = (const int*)d_in[10];
    const float* so   = (const float*)d_in[11];
    float* out = (float*)d_out;

    const int SMEM_NK = (2 * ASZ + 2 * BSZN) * 4;   // 110592 B
    const int SMEM_KN = (2 * ASZ + 2 * BSZK) * 4;   // 108544 B
    cudaFuncSetAttribute(qkv_mma,   cudaFuncAttributeMaxDynamicSharedMemorySize, SMEM_NK);
    cudaFuncSetAttribute(score_mma, cudaFuncAttributeMaxDynamicSharedMemorySize, SMEM_NK);
    cudaFuncSetAttribute(pv_mma,    cudaFuncAttributeMaxDynamicSharedMemorySize, SMEM_KN);
    cudaFuncSetAttribute(o_mma,     cudaFuncAttributeMaxDynamicSharedMemorySize, SMEM_NK);

    float* Xc = nullptr;   cudaGetSymbolAddress((void**)&Xc,   g_Xc);
    float* Wqkv = nullptr; cudaGetSymbolAddress((void**)&Wqkv, g_Wqkv);
    float* Wof = nullptr;  cudaGetSymbolAddress((void**)&Wof,  g_Wof);

    // prep: round activations to tf32 once; convert int weights to float (exact)
    cvtx_kernel<<<(2048 * 4096 / 4 + 255) / 256, 256>>>(X, Xc, 2048 * 4096 / 4);
    i2f_kernel<<<(4096 * 4096 / 4 + 255) / 256, 256>>>(wq, Wqkv,                 4096 * 4096 / 4);
    i2f_kernel<<<(1024 * 4096 / 4 + 255) / 256, 256>>>(wk, Wqkv + 4096 * 4096,   1024 * 4096 / 4);
    i2f_kernel<<<(1024 * 4096 / 4 + 255) / 256, 256>>>(wv, Wqkv + 5120 * 4096,   1024 * 4096 / 4);
    i2f_kernel<<<(4096 * 4096 / 4 + 255) / 256, 256>>>(wo, Wof,                  4096 * 4096 / 4);

    qkv_mma<<<dim3(48, 8), 256, SMEM_NK>>>(sq, bq, sk, bk, sv);
    score_mma<<<dim3(8, 4, 64), 256, SMEM_NK>>>(mask);
    softmax_kernel<<<8192, 256>>>();
    pv_mma<<<dim3(1, 4, 64), 256, SMEM_KN>>>();
    o_mma<<<dim3(32, 8), 256, SMEM_NK>>>(so, out);
}

// round 7
// speedup vs baseline: 4.5336x; 1.1706x over previous
#include <cuda_runtime.h>
#include <cstdint>

// B=2, S=1024, H=4096, NH=32, NKV=8, HD=128, GROUPS=4, M=B*S=2048
// GEMMs on mma.sync.m16n8k8.tf32. Weights exact in tf32; activations RNA-rounded
// once at producer epilogues. Attention mid (QK^T + softmax + PV) fused into a
// causal flash kernel: no materialized P, lower-triangle work only.

// ---------------- scratch (static __device__, no allocations) ----------------
__device__ static float g_Xc[2048 * 4096];            //  32 MB tf32-rounded X
__device__ static float g_Wqkv[6144 * 4096];          // 100 MB float weights (q,k,v)
__device__ static float g_Wof[4096 * 4096];           //  64 MB float Wo
__device__ static float g_Q[2 * 32 * 1024 * 128];     //  [B,NH,S,HD]  tf32 vals
__device__ static float g_K[2 * 8 * 1024 * 128];      //  [B,NKV,S,HD]
__device__ static float g_V[2 * 8 * 1024 * 128];
__device__ static float g_AO[2048 * 4096];            //  [B*S, NH*HD] tf32 vals

// ---------------- helpers ----------------
__device__ __forceinline__ float to_tf32(float x) {
    uint32_t u;
    asm("cvt.rna.tf32.f32 %0, %1;" : "=r"(u) : "f"(x));
    return __uint_as_float(u);
}
__device__ __forceinline__ void cpa16(float* dst, const float* src) {
    uint32_t s = static_cast<uint32_t>(__cvta_generic_to_shared(dst));
    asm volatile("cp.async.cg.shared.global [%0], [%1], 16;\n" :: "r"(s), "l"(src));
}
#define CP_COMMIT() asm volatile("cp.async.commit_group;\n")
#define CP_WAIT1()  asm volatile("cp.async.wait_group 1;\n")
#define CP_WAIT0()  asm volatile("cp.async.wait_group 0;\n")

__device__ __forceinline__ void mma_tf32(float d[4], const uint32_t a[4], const uint32_t b[2]) {
    asm volatile(
        "mma.sync.aligned.m16n8k8.row.col.f32.tf32.tf32.f32 "
        "{%0,%1,%2,%3},{%4,%5,%6,%7},{%8,%9},{%0,%1,%2,%3};\n"
        : "+f"(d[0]), "+f"(d[1]), "+f"(d[2]), "+f"(d[3])
        : "r"(a[0]), "r"(a[1]), "r"(a[2]), "r"(a[3]), "r"(b[0]), "r"(b[1]));
}

// smem layouts (floats): A [256][36], B_nk [128][36]
#define ASZ  (256 * 36)
#define BSZN (128 * 36)

__device__ __forceinline__ void load_tileA(float* dst, const float* src, int rs, int t) {
    int c = t & 7, mb = t >> 3;
#pragma unroll
    for (int p = 0; p < 8; ++p) {
        int m = mb + 32 * p;
        cpa16(dst + m * 36 + 4 * c, src + (size_t)m * rs + 4 * c);
    }
}
__device__ __forceinline__ void load_tileB_nk(float* dst, const float* src, int rs, int t) {
    int c = t & 7, nb = t >> 3;
#pragma unroll
    for (int p = 0; p < 4; ++p) {
        int n = nb + 32 * p;
        cpa16(dst + n * 36 + 4 * c, src + (size_t)n * rs + 4 * c);
    }
}

// compute one k32 chunk (B in [n][36] layout). warp tile 64x64.
__device__ __forceinline__ void compute_k32(const float* sA, const float* sB,
                                            float acc[4][8][4], int lane, int wm, int wn) {
    const int lr = lane >> 2, lc = lane & 3;
#pragma unroll
    for (int s = 0; s < 4; ++s) {
        uint32_t af[4][4], bf[8][2];
#pragma unroll
        for (int i = 0; i < 4; ++i) {
            const float* p = sA + (wm + 16 * i + lr) * 36 + 8 * s + lc;
            af[i][0] = __float_as_uint(p[0]);
            af[i][1] = __float_as_uint(p[8 * 36]);
            af[i][2] = __float_as_uint(p[4]);
            af[i][3] = __float_as_uint(p[8 * 36 + 4]);
        }
#pragma unroll
        for (int j = 0; j < 8; ++j) {
            const float* p = sB + (wn + 8 * j + lr) * 36 + 8 * s + lc;
            bf[j][0] = __float_as_uint(p[0]);
            bf[j][1] = __float_as_uint(p[4]);
        }
#pragma unroll
        for (int i = 0; i < 4; ++i)
#pragma unroll
            for (int j = 0; j < 8; ++j)
                mma_tf32(acc[i][j], af[i], bf[j]);
    }
}

// ---------------- prep kernels ----------------
__global__ __launch_bounds__(256) void i2f_kernel(const int* __restrict__ src,
                                                  float* __restrict__ dst, int n4) {
    int i = blockIdx.x * 256 + threadIdx.x;
    if (i < n4) {
        int4 v = reinterpret_cast<const int4*>(src)[i];
        reinterpret_cast<float4*>(dst)[i] =
            make_float4((float)v.x, (float)v.y, (float)v.z, (float)v.w);
    }
}
__global__ __launch_bounds__(256) void cvtx_kernel(const float* __restrict__ src,
                                                   float* __restrict__ dst, int n4) {
    int i = blockIdx.x * 256 + threadIdx.x;
    if (i < n4) {
        float4 v = reinterpret_cast<const float4*>(src)[i];
        v.x = to_tf32(v.x); v.y = to_tf32(v.y); v.z = to_tf32(v.z); v.w = to_tf32(v.w);
        reinterpret_cast<float4*>(dst)[i] = v;
    }
}

// ---------------- GEMM 1: fused QKV projection ---------------- grid (48, 8)
__global__ __launch_bounds__(256) void qkv_mma(
    const float* __restrict__ sq, const float* __restrict__ bq,
    const float* __restrict__ sk, const float* __restrict__ bk,
    const float* __restrict__ sv)
{
    extern __shared__ float sm[];
    float* sA = sm;
    float* sB = sm + 2 * ASZ;
    const int t = threadIdx.x, lane = t & 31, w = t >> 5;
    const int wm = (w >> 1) * 64, wn = (w & 1) * 64;
    const int m0 = blockIdx.y * 256, n0 = blockIdx.x * 128;

    float acc[4][8][4];
#pragma unroll
    for (int i = 0; i < 4; ++i)
#pragma unroll
        for (int j = 0; j < 8; ++j)
#pragma unroll
            for (int q = 0; q < 4; ++q) acc[i][j][q] = 0.f;

    const float* Ab = g_Xc + (size_t)m0 * 4096;
    const float* Bb = g_Wqkv + (size_t)n0 * 4096;

    load_tileA(sA, Ab, 4096, t);
    load_tileB_nk(sB, Bb, 4096, t);
    CP_COMMIT();
    for (int it = 0; it < 128; ++it) {
        if (it + 1 < 128) {
            int nb = (it + 1) & 1;
            load_tileA(sA + nb * ASZ, Ab + (it + 1) * 32, 4096, t);
            load_tileB_nk(sB + nb * BSZN, Bb + (it + 1) * 32, 4096, t);
            CP_COMMIT();
            CP_WAIT1();
        } else CP_WAIT0();
        __syncthreads();
        int buf = it & 1;
        compute_k32(sA + buf * ASZ, sB + buf * BSZN, acc, lane, wm, wn);
        __syncthreads();
    }

    int region, nloc;
    const float* scale; const float* bias;
    if (n0 < 4096)      { region = 0; nloc = n0;        scale = sq; bias = bq; }
    else if (n0 < 5120) { region = 1; nloc = n0 - 4096; scale = sk; bias = bk; }
    else                { region = 2; nloc = n0 - 5120; scale = sv; bias = nullptr; }
    const int head = nloc >> 7;
    const int lr = lane >> 2, lc = lane & 3;
#pragma unroll
    for (int j = 0; j < 8; ++j) {
        int col = wn + 8 * j + 2 * lc;
        int nl = nloc + col;
        float sc0 = scale[nl], sc1 = scale[nl + 1];
        float bb0 = bias ? bias[nl] : 0.f, bb1 = bias ? bias[nl + 1] : 0.f;
#pragma unroll
        for (int i = 0; i < 4; ++i) {
#pragma unroll
            for (int h2 = 0; h2 < 2; ++h2) {
                int m = m0 + wm + 16 * i + lr + 8 * h2;
                int b = m >> 10, s = m & 1023;
                float v0 = to_tf32(acc[i][j][2 * h2 + 0] * sc0 + bb0);
                float v1 = to_tf32(acc[i][j][2 * h2 + 1] * sc1 + bb1);
                float* dst;
                if (region == 0)      dst = g_Q + ((size_t)((b * 32 + head) * 1024 + s)) * 128 + col;
                else if (region == 1) dst = g_K + ((size_t)((b * 8 + head) * 1024 + s)) * 128 + col;
                else                  dst = g_V + ((size_t)((b * 8 + head) * 1024 + s)) * 128 + col;
                *reinterpret_cast<float2*>(dst) = make_float2(v0, v1);
            }
        }
    }
}

// ---------------- fused causal flash attention ---------------- grid (64, 8)
// CTA: (z, m-tile of 128 rows). 8 warps x 16 rows. K/V in 64-key double-buffered
// tiles; Q fragments register-resident; online softmax; P restaged via smem.
#define FK_PAD 132      // sK row pitch (conflict-free for [n][d] B-frag reads)
#define FV_PAD 136      // sV row pitch (conflict-free for [k][d] B-frag reads)
#define FP_PAD 68       // sP row pitch
#define SK_TILE (64 * FK_PAD)
#define SV_TILE (64 * FV_PAD)
#define FLASH_SMEM ((2 * SK_TILE + 2 * SV_TILE + 128 * FP_PAD) * 4)

__device__ __forceinline__ void flash_loadKV(float* dK, float* dV,
                                             const float* Kp, const float* Vp,
                                             int n0, int t) {
    int c = t & 31, rb = t >> 5;
#pragma unroll
    for (int p = 0; p < 8; ++p) {
        int r = rb + 8 * p;
        cpa16(dK + r * FK_PAD + 4 * c, Kp + (size_t)(n0 + r) * 128 + 4 * c);
        cpa16(dV + r * FV_PAD + 4 * c, Vp + (size_t)(n0 + r) * 128 + 4 * c);
    }
}

__global__ __launch_bounds__(256, 1) void flash_mma()
{
    extern __shared__ float sm[];
    float* sK = sm;                       // [2][64][FK_PAD]
    float* sV = sm + 2 * SK_TILE;         // [2][64][FV_PAD]
    float* sP = sV + 2 * SV_TILE;         // [128][FP_PAD]

    const int t = threadIdx.x, lane = t & 31, w = t >> 5;
    const int lr = lane >> 2, lc = lane & 3;
    const int z = blockIdx.x, mt = 7 - blockIdx.y;   // heavy tiles first
    const int m0 = mt * 128;
    const int niter = 2 * mt + 2;
    const int b = z >> 5, h = z & 31, kvh = h >> 2;

    const float* Qp = g_Q + (size_t)(b * 32 + h) * 131072;
    const float* Kp = g_K + (size_t)(b * 8 + kvh) * 131072;
    const float* Vp = g_V + (size_t)(b * 8 + kvh) * 131072;

    // stage Q tile: rows 0-63 -> sK buf0, rows 64-127 -> sV buf0
    {
        int c = t & 31, rb = t >> 5;
#pragma unroll
        for (int p = 0; p < 16; ++p) {
            int r = rb + 8 * p;
            float* dst = (r < 64) ? (sK + r * FK_PAD + 4 * c)
                                  : (sV + (r - 64) * FV_PAD + 4 * c);
            cpa16(dst, Qp + (size_t)(m0 + r) * 128 + 4 * c);
        }
        CP_COMMIT(); CP_WAIT0();
    }
    __syncthreads();

    // extract Q fragments (held in regs for the whole kernel)
    uint32_t qf[16][4];
    {
        const float* base; int pad, rb2;
        if (w < 4) { base = sK; pad = FK_PAD; rb2 = 16 * w; }
        else       { base = sV; pad = FV_PAD; rb2 = 16 * w - 64; }
#pragma unroll
        for (int s = 0; s < 16; ++s) {
            const float* p = base + (rb2 + lr) * pad + 8 * s + lc;
            qf[s][0] = __float_as_uint(p[0]);
            qf[s][1] = __float_as_uint(p[8 * pad]);
            qf[s][2] = __float_as_uint(p[4]);
            qf[s][3] = __float_as_uint(p[8 * pad + 4]);
        }
    }
    __syncthreads();

    float oacc[16][4];
#pragma unroll
    for (int j = 0; j < 16; ++j)
#pragma unroll
        for (int q = 0; q < 4; ++q) oacc[j][q] = 0.f;
    float mrow[2] = {-1e38f, -1e38f};
    float lrow[2] = {0.f, 0.f};

    flash_loadKV(sK, sV, Kp, Vp, 0, t);
    CP_COMMIT();

    const float sscale = 0.08838834764831845f;   // 1/sqrt(128)

    for (int it = 0; it < niter; ++it) {
        if (it + 1 < niter) {
            int nb = (it + 1) & 1;
            flash_loadKV(sK + nb * SK_TILE, sV + nb * SV_TILE, Kp, Vp, (it + 1) * 64, t);
            CP_COMMIT(); CP_WAIT1();
        } else CP_WAIT0();
        __syncthreads();

        const int buf = it & 1;
        const float* K0 = sK + buf * SK_TILE;
        const float* V0 = sV + buf * SV_TILE;
        const int n0 = it * 64;

        // ---- S = Q K^T (warp: 16 rows x 64 keys)
        float sacc[8][4];
#pragma unroll
        for (int j = 0; j < 8; ++j)
#pragma unroll
            for (int q = 0; q < 4; ++q) sacc[j][q] = 0.f;
#pragma unroll
        for (int s = 0; s < 16; ++s) {
#pragma unroll
            for (int j = 0; j < 8; ++j) {
                uint32_t bf[2];
                const float* p = K0 + (8 * j + lr) * FK_PAD + 8 * s + lc;
                bf[0] = __float_as_uint(p[0]);
                bf[1] = __float_as_uint(p[4]);
                mma_tf32(sacc[j], qf[s], bf);
            }
        }

        // ---- scale + causal mask + online softmax (rows lr, lr+8 of stripe)
#pragma unroll
        for (int d = 0; d < 2; ++d) {
            const int grow = m0 + 16 * w + lr + 8 * d;
            float rm = -1e38f;
#pragma unroll
            for (int j = 0; j < 8; ++j) {
                int c0 = n0 + 8 * j + 2 * lc;
                float v0 = sacc[j][2 * d]     * sscale;
                float v1 = sacc[j][2 * d + 1] * sscale;
                if (c0     > grow) v0 = -1e30f;
                if (c0 + 1 > grow) v1 = -1e30f;
                sacc[j][2 * d]     = v0;
                sacc[j][2 * d + 1] = v1;
                rm = fmaxf(rm, fmaxf(v0, v1));
            }
            rm = fmaxf(rm, __shfl_xor_sync(0xffffffffu, rm, 1));
            rm = fmaxf(rm, __shfl_xor_sync(0xffffffffu, rm, 2));
            float newm = fmaxf(mrow[d], rm);
            float f = __expf(mrow[d] - newm);
            float rs = 0.f;
#pragma unroll
            for (int j = 0; j < 8; ++j) {
                float p0 = __expf(sacc[j][2 * d]     - newm);
                float p1 = __expf(sacc[j][2 * d + 1] - newm);
                rs += p0 + p1;
                float* pp = sP + (16 * w + lr + 8 * d) * FP_PAD + 8 * j + 2 * lc;
                pp[0] = to_tf32(p0);
                pp[1] = to_tf32(p1);
            }
            rs += __shfl_xor_sync(0xffffffffu, rs, 1);
            rs += __shfl_xor_sync(0xffffffffu, rs, 2);
            lrow[d] = lrow[d] * f + rs;
            mrow[d] = newm;
#pragma unroll
            for (int j2 = 0; j2 < 16; ++j2) {
                oacc[j2][2 * d]     *= f;
                oacc[j2][2 * d + 1] *= f;
            }
        }
        __syncwarp();

        // ---- O += P V   (warp: 16 rows x 128 d-cols, k=64)
#pragma unroll
        for (int s = 0; s < 8; ++s) {
            uint32_t af[4];
            const float* pa = sP + (16 * w + lr) * FP_PAD + 8 * s + lc;
            af[0] = __float_as_uint(pa[0]);
            af[1] = __float_as_uint(pa[8 * FP_PAD]);
            af[2] = __float_as_uint(pa[4]);
            af[3] = __float_as_uint(pa[8 * FP_PAD + 4]);
#pragma unroll
            for (int j2 = 0; j2 < 16; ++j2) {
                uint32_t bf[2];
                const float* pb = V0 + (8 * s + lc) * FV_PAD + 8 * j2 + lr;
                bf[0] = __float_as_uint(pb[0]);
                bf[1] = __float_as_uint(pb[4 * FV_PAD]);
                mma_tf32(oacc[j2], af, bf);
            }
        }
        __syncthreads();
    }

    // ---- epilogue: O /= l, tf32 round, write [B*S, NH*HD]
#pragma unroll
    for (int d = 0; d < 2; ++d) {
        float inv = 1.f / lrow[d];
        int grow = m0 + 16 * w + lr + 8 * d;
        float* orow = g_AO + ((size_t)(b * 1024 + grow)) * 4096 + h * 128;
#pragma unroll
        for (int j2 = 0; j2 < 16; ++j2) {
            float2 o = make_float2(to_tf32(oacc[j2][2 * d]     * inv),
                                   to_tf32(oacc[j2][2 * d + 1] * inv));
            *reinterpret_cast<float2*>(orow + 8 * j2 + 2 * lc) = o;
        }
    }
}

// ---------------- GEMM 4: out = AO @ Wo^T * so ---------------- grid (32, 8)
__global__ __launch_bounds__(256) void o_mma(const float* __restrict__ so,
                                             float* __restrict__ out)
{
    extern __shared__ float sm[];
    float* sA = sm;
    float* sB = sm + 2 * ASZ;
    const int t = threadIdx.x, lane = t & 31, w = t >> 5;
    const int wm = (w >> 1) * 64, wn = (w & 1) * 64;
    const int m0 = blockIdx.y * 256, n0 = blockIdx.x * 128;

    float acc[4][8][4];
#pragma unroll
    for (int i = 0; i < 4; ++i)
#pragma unroll
        for (int j = 0; j < 8; ++j)
#pragma unroll
            for (int q = 0; q < 4; ++q) acc[i][j][q] = 0.f;

    const float* Ab = g_AO + (size_t)m0 * 4096;
    const float* Bb = g_Wof + (size_t)n0 * 4096;
    load_tileA(sA, Ab, 4096, t);
    load_tileB_nk(sB, Bb, 4096, t);
    CP_COMMIT();
    for (int it = 0; it < 128; ++it) {
        if (it + 1 < 128) {
            int nb = (it + 1) & 1;
            load_tileA(sA + nb * ASZ, Ab + (it + 1) * 32, 4096, t);
            load_tileB_nk(sB + nb * BSZN, Bb + (it + 1) * 32, 4096, t);
            CP_COMMIT();
            CP_WAIT1();
        } else CP_WAIT0();
        __syncthreads();
        int buf = it & 1;
        compute_k32(sA + buf * ASZ, sB + buf * BSZN, acc, lane, wm, wn);
        __syncthreads();
    }

    const int lr = lane >> 2, lc = lane & 3;
#pragma unroll
    for (int j = 0; j < 8; ++j) {
        int col = n0 + wn + 8 * j + 2 * lc;
        float sc0 = so[col], sc1 = so[col + 1];
#pragma unroll
        for (int i = 0; i < 4; ++i) {
#pragma unroll
            for (int h2 = 0; h2 < 2; ++h2) {
                int m = m0 + wm + 16 * i + lr + 8 * h2;
                float2 o = make_float2(acc[i][j][2 * h2 + 0] * sc0,
                                       acc[i][j][2 * h2 + 1] * sc1);
                *reinterpret_cast<float2*>(out + (size_t)m * 4096 + col) = o;
            }
        }
    }
}

// =============================================================================
extern "C" void kernel_launch(void* const* d_in, const int* in_sizes, int n_in,
                              void* d_out, int out_size)
{
    const float* X    = (const float*)d_in[0];
    const float* sq   = (const float*)d_in[3];
    const float* bq   = (const float*)d_in[4];
    const float* sk   = (const float*)d_in[6];
    const float* bk   = (const float*)d_in[7];
    const float* sv   = (const float*)d_in[9];
    const float* so   = (const float*)d_in[11];
    const int*   wq   = (const int*)d_in[2];
    const int*   wk   = (const int*)d_in[5];
    const int*   wv   = (const int*)d_in[8];
    const int*   wo   = (const int*)d_in[10];
    float* out = (float*)d_out;

    const int SMEM_NK = (2 * ASZ + 2 * BSZN) * 4;   // 110592 B
    cudaFuncSetAttribute(qkv_mma,   cudaFuncAttributeMaxDynamicSharedMemorySize, SMEM_NK);
    cudaFuncSetAttribute(o_mma,     cudaFuncAttributeMaxDynamicSharedMemorySize, SMEM_NK);
    cudaFuncSetAttribute(flash_mma, cudaFuncAttributeMaxDynamicSharedMemorySize, FLASH_SMEM);

    float* Xc = nullptr;   cudaGetSymbolAddress((void**)&Xc,   g_Xc);
    float* Wqkv = nullptr; cudaGetSymbolAddress((void**)&Wqkv, g_Wqkv);
    float* Wof = nullptr;  cudaGetSymbolAddress((void**)&Wof,  g_Wof);

    cvtx_kernel<<<(2048 * 4096 / 4 + 255) / 256, 256>>>(X, Xc, 2048 * 4096 / 4);
    i2f_kernel<<<(4096 * 4096 / 4 + 255) / 256, 256>>>(wq, Wqkv,               4096 * 4096 / 4);
    i2f_kernel<<<(1024 * 4096 / 4 + 255) / 256, 256>>>(wk, Wqkv + 4096 * 4096, 1024 * 4096 / 4);
    i2f_kernel<<<(1024 * 4096 / 4 + 255) / 256, 256>>>(wv, Wqkv + 5120 * 4096, 1024 * 4096 / 4);
    i2f_kernel<<<(4096 * 4096 / 4 + 255) / 256, 256>>>(wo, Wof,                4096 * 4096 / 4);

    qkv_mma<<<dim3(48, 8), 256, SMEM_NK>>>(sq, bq, sk, bk, sv);
    flash_mma<<<dim3(64, 8), 256, FLASH_SMEM>>>();
    o_mma<<<dim3(32, 8), 256, SMEM_NK>>>(so, out);
}